// round 9
// baseline (speedup 1.0000x reference)
#include <cuda_runtime.h>

#define BB 8
#define LL 32768
#define DD 128
#define NTOK (BB * LL)
#define TILE 2048
#define NTILES (NTOK / TILE)

__device__ ulonglong2 g_items[NTOK];

__device__ __forceinline__ unsigned int fmono(float f) {
    unsigned int b = __float_as_uint(f);
    return (b & 0x80000000u) ? ~b : (b | 0x80000000u);
}
__device__ __forceinline__ bool item_gt(const ulonglong2& a, const ulonglong2& b) {
    return (a.x > b.x) || (a.x == b.x && a.y > b.y);
}
__device__ __forceinline__ void ce(ulonglong2& a, ulonglong2& b, bool asc) {
    if (item_gt(a, b) == asc) { ulonglong2 t = a; a = b; b = t; }
}
__device__ __forceinline__ ulonglong2 shfl_item(ulonglong2 v, int m) {
    ulonglong2 o;
    o.x = __shfl_xor_sync(0xffffffffu, v.x, m);
    o.y = __shfl_xor_sync(0xffffffffu, v.y, m);
    return o;
}

// ---------------------------------------------------------------------------
// Item construction — rounding model LOCKED (R5/R6 verified bit-exact, C_A):
//   per projection h: 4 interleaved FMA accumulators (u = d mod 4), ascending
//   d, combine (a0+a1)+(a2+a3); key = (k0 + 2*k1) + 4*k2.
// ---------------------------------------------------------------------------
__device__ __forceinline__ ulonglong2 make_item(const float* __restrict__ row,
                                                const float* __restrict__ sal,
                                                int idx_in_batch) {
    float a[3][4];
#pragma unroll
    for (int h = 0; h < 3; h++)
#pragma unroll
        for (int u = 0; u < 4; u++) a[h][u] = 0.f;
    float sq = 0.f;
#pragma unroll
    for (int j = 0; j < DD; j += 4) {
        float4 p = *reinterpret_cast<const float4*>(row + j);
#pragma unroll
        for (int u = 0; u < 4; u++) {
            float pv = (&p.x)[u];
            a[0][u] = __fmaf_rn(pv, sal[(j + u) * 3 + 0], a[0][u]);
            a[1][u] = __fmaf_rn(pv, sal[(j + u) * 3 + 1], a[1][u]);
            a[2][u] = __fmaf_rn(pv, sal[(j + u) * 3 + 2], a[2][u]);
            sq      = __fmaf_rn(pv, pv, sq);
        }
    }
    float k0 = __fadd_rn(__fadd_rn(a[0][0], a[0][1]), __fadd_rn(a[0][2], a[0][3]));
    float k1 = __fadd_rn(__fadd_rn(a[1][0], a[1][1]), __fadd_rn(a[1][2], a[1][3]));
    float k2 = __fadd_rn(__fadd_rn(a[2][0], a[2][1]), __fadd_rn(a[2][2], a[2][3]));
    float key = __fadd_rn(__fadd_rn(k0, __fmul_rn(2.f, k1)), __fmul_rn(4.f, k2));
    float nrm = __fsqrt_rn(sq);
    ulonglong2 it;
    it.x = ((unsigned long long)fmono(key) << 32) | (unsigned long long)fmono(nrm);
    it.y = (unsigned long long)idx_in_batch;
    return it;
}

// ---------------------------------------------------------------------------
// Fused kernel 1: compute keys for a 2048-token tile AND fully bitonic-sort
// the tile (k = 2..2048). Thread owns tokens base+tid and base+tid+1024.
// ---------------------------------------------------------------------------
__global__ void __launch_bounds__(1024) key_first_kernel(const float* __restrict__ pts,
                                                         const float* __restrict__ alpha) {
    __shared__ float sal[DD * 3];
    __shared__ ulonglong2 s[TILE];
    int tid = threadIdx.x;
    int base = blockIdx.x * TILE;

    for (int i = tid; i < DD * 3; i += 1024) sal[i] = alpha[i];
    __syncthreads();

    ulonglong2 x = make_item(pts + (size_t)(base + tid) * DD, sal,
                             (base + tid) & (LL - 1));
    ulonglong2 y = make_item(pts + (size_t)(base + tid + 1024) * DD, sal,
                             (base + tid + 1024) & (LL - 1));

    // k = 2..32: warp-local
#pragma unroll
    for (int k = 2; k <= 32; k <<= 1) {
        bool asc = (tid & k) == 0;
#pragma unroll
        for (int j = k >> 1; j; j >>= 1) {
            ulonglong2 ox = shfl_item(x, j), oy = shfl_item(y, j);
            bool wmin = ((tid & j) == 0) == asc;
            if (item_gt(x, ox) == wmin) x = ox;
            if (item_gt(y, oy) == wmin) y = oy;
        }
    }

    // k = 64..2048: smem for j>=32, shuffles for j<=16
    for (int k = 64; k <= TILE; k <<= 1) {
        s[tid] = x; s[tid + 1024] = y;
        __syncthreads();
        for (int j = k >> 1; j >= 32; j >>= 1) {
            int i = 2 * tid - (tid & (j - 1));
            int l = i + j;
            bool asc = (((unsigned)(base + i) & (LL - 1)) & (unsigned)k) == 0;
            ulonglong2 a = s[i], b = s[l];
            if (item_gt(a, b) == asc) { s[i] = b; s[l] = a; }
            __syncthreads();
        }
        x = s[tid]; y = s[tid + 1024];
        bool ascx = (((unsigned)(base + tid) & (LL - 1)) & (unsigned)k) == 0;
        bool ascy = (((unsigned)(base + tid + 1024) & (LL - 1)) & (unsigned)k) == 0;
#pragma unroll
        for (int j = 16; j; j >>= 1) {
            ulonglong2 ox = shfl_item(x, j), oy = shfl_item(y, j);
            bool wminx = ((tid & j) == 0) == ascx;
            bool wminy = ((tid & j) == 0) == ascy;
            if (item_gt(x, ox) == wminx) x = ox;
            if (item_gt(y, oy) == wminy) y = oy;
        }
    }
    g_items[base + tid] = x;
    g_items[base + tid + 1024] = y;
}

// ---------------------------------------------------------------------------
// Fused global pass for stage k: all strides >= 2048 in registers.
// ---------------------------------------------------------------------------
template <int M>
__global__ void __launch_bounds__(256) bitonic_global_fused(int k) {
    int g = blockIdx.x * blockDim.x + threadIdx.x;
    int high = g >> 11, low = g & 2047;
    unsigned base = (unsigned)high * (M * 2048) + (unsigned)low;

    ulonglong2 v[M];
#pragma unroll
    for (int t = 0; t < M; t++) v[t] = g_items[base + t * 2048];

    bool asc = ((base & (LL - 1)) & (unsigned)k) == 0;
#pragma unroll
    for (int s = M / 2; s; s >>= 1) {
#pragma unroll
        for (int t = 0; t < M; t++) {
            if (!(t & s)) ce(v[t], v[t | s], asc);
        }
    }
#pragma unroll
    for (int t = 0; t < M; t++) g_items[base + t * 2048] = v[t];
}

// ---------------------------------------------------------------------------
// Tile merge for stage k (k > TILE, uniform direction). 512 threads x 4:
// strides 1024,512 in regs; 256..32 in smem; 16..1 via shuffles.
// ---------------------------------------------------------------------------
__global__ void __launch_bounds__(512) bitonic_shared_merge(int k) {
    __shared__ ulonglong2 s[TILE];
    int base = blockIdx.x * TILE;
    int t = threadIdx.x;
    bool asc = (((unsigned)base & (LL - 1)) & (unsigned)k) == 0;

    ulonglong2 v[4];
#pragma unroll
    for (int i = 0; i < 4; i++) v[i] = g_items[base + t + i * 512];

    ce(v[0], v[2], asc); ce(v[1], v[3], asc);
    ce(v[0], v[1], asc); ce(v[2], v[3], asc);

#pragma unroll
    for (int i = 0; i < 4; i++) s[t + i * 512] = v[i];
    __syncthreads();

    for (int j = 256; j >= 32; j >>= 1) {
#pragma unroll
        for (int qq = 0; qq < 2; qq++) {
            int q = t + qq * 512;
            int i = 2 * q - (q & (j - 1));
            int l = i + j;
            ulonglong2 a = s[i], b = s[l];
            if (item_gt(a, b) == asc) { s[i] = b; s[l] = a; }
        }
        __syncthreads();
    }

    int w = t >> 5, l = t & 31;
#pragma unroll
    for (int c = 0; c < 4; c++) {
        int idx = w * 128 + c * 32 + l;
        ulonglong2 x = s[idx];
#pragma unroll
        for (int j = 16; j; j >>= 1) {
            ulonglong2 ox = shfl_item(x, j);
            bool wmin = ((l & j) == 0) == asc;
            if (item_gt(x, ox) == wmin) x = ox;
        }
        g_items[base + idx] = x;
    }
}

// ---------------------------------------------------------------------------
// FINAL merge (k = 32768) fused with the output copy: after the last shuffle
// each thread knows (dst position e, source row x.y) for 4 rows -> copy the
// 512B rows pts->out directly and write the index tail. No g_items/g_inv
// write-back needed.
// ---------------------------------------------------------------------------
__global__ void __launch_bounds__(512) bitonic_merge_final(const float* __restrict__ pts,
                                                           float* __restrict__ out,
                                                           int write_idx) {
    __shared__ ulonglong2 s[TILE];
    int base = blockIdx.x * TILE;
    int t = threadIdx.x;
    bool asc = true;  // k = 32768 == LL -> (base & (LL-1)) & k == 0 always

    ulonglong2 v[4];
#pragma unroll
    for (int i = 0; i < 4; i++) v[i] = g_items[base + t + i * 512];

    ce(v[0], v[2], asc); ce(v[1], v[3], asc);
    ce(v[0], v[1], asc); ce(v[2], v[3], asc);

#pragma unroll
    for (int i = 0; i < 4; i++) s[t + i * 512] = v[i];
    __syncthreads();

    for (int j = 256; j >= 32; j >>= 1) {
#pragma unroll
        for (int qq = 0; qq < 2; qq++) {
            int q = t + qq * 512;
            int i = 2 * q - (q & (j - 1));
            int l = i + j;
            ulonglong2 a = s[i], b = s[l];
            if (item_gt(a, b) == asc) { s[i] = b; s[l] = a; }
        }
        __syncthreads();
    }

    int w = t >> 5, l = t & 31;
#pragma unroll
    for (int c = 0; c < 4; c++) {
        int idx = w * 128 + c * 32 + l;
        ulonglong2 x = s[idx];
#pragma unroll
        for (int j = 16; j; j >>= 1) {
            ulonglong2 ox = shfl_item(x, j);
            bool wmin = ((l & j) == 0) == asc;
            if (item_gt(x, ox) == wmin) x = ox;
        }
        int e = base + idx;           // final output position
        int b = e >> 15;              // batch
        int src = (int)x.y;           // source row within batch
        const float4* sp = reinterpret_cast<const float4*>(
            pts + ((size_t)b * LL + (size_t)src) * DD);
        float4* dp = reinterpret_cast<float4*>(out + (size_t)e * DD);
#pragma unroll
        for (int q = 0; q < DD / 4; q++) dp[q] = sp[q];
        if (write_idx) out[(size_t)NTOK * DD + e] = (float)src;
    }
}

extern "C" void kernel_launch(void* const* d_in, const int* in_sizes, int n_in,
                              void* d_out, int out_size) {
    (void)n_in;
    const float* pts   = (const float*)d_in[0];
    const float* alpha = (const float*)d_in[1];
    if (in_sizes[0] < in_sizes[1]) { pts = (const float*)d_in[1]; alpha = (const float*)d_in[0]; }

    float* out = (float*)d_out;
    int write_idx = (out_size >= NTOK * DD + NTOK) ? 1 : 0;

    key_first_kernel<<<NTILES, 1024>>>(pts, alpha);

    bitonic_global_fused<2><<<(NTOK / 2) / 256, 256>>>(4096);
    bitonic_shared_merge<<<NTILES, 512>>>(4096);

    bitonic_global_fused<4><<<(NTOK / 4) / 256, 256>>>(8192);
    bitonic_shared_merge<<<NTILES, 512>>>(8192);

    bitonic_global_fused<8><<<(NTOK / 8) / 256, 256>>>(16384);
    bitonic_shared_merge<<<NTILES, 512>>>(16384);

    bitonic_global_fused<16><<<(NTOK / 16) / 256, 256>>>(32768);
    bitonic_merge_final<<<NTILES, 512>>>(pts, out, write_idx);
}

// round 10
// speedup vs baseline: 2.0375x; 2.0375x over previous
#include <cuda_runtime.h>

#define BB 8
#define LL 32768
#define DD 128
#define NTOK (BB * LL)
#define TILE 2048
#define NTILES (NTOK / TILE)

__device__ ulonglong2 g_items[NTOK];

__device__ __forceinline__ unsigned int fmono(float f) {
    unsigned int b = __float_as_uint(f);
    return (b & 0x80000000u) ? ~b : (b | 0x80000000u);
}
__device__ __forceinline__ bool item_gt(const ulonglong2& a, const ulonglong2& b) {
    return (a.x > b.x) || (a.x == b.x && a.y > b.y);
}
__device__ __forceinline__ void ce(ulonglong2& a, ulonglong2& b, bool asc) {
    if (item_gt(a, b) == asc) { ulonglong2 t = a; a = b; b = t; }
}
__device__ __forceinline__ ulonglong2 shfl_item(ulonglong2 v, int m) {
    ulonglong2 o;
    o.x = __shfl_xor_sync(0xffffffffu, v.x, m);
    o.y = __shfl_xor_sync(0xffffffffu, v.y, m);
    return o;
}

// ---------------------------------------------------------------------------
// Key kernel — rounding model LOCKED (R5/R6 verified bit-exact, C_A):
//   per projection h: 4 interleaved FMA accumulators (u = d mod 4), ascending
//   d, combine (a0+a1)+(a2+a3); key = (k0 + 2*k1) + 4*k2.
// Staging through smem (coalesced float4 loads). DO NOT change access pattern:
// per-lane direct row reads caused an 8x sector-amplification regression (R9).
// ---------------------------------------------------------------------------
__global__ void __launch_bounds__(128) key_kernel(const float* __restrict__ pts,
                                                  const float* __restrict__ alpha) {
    __shared__ float sal[DD * 3];
    __shared__ float tile[128][33];
    int tid = threadIdx.x;
    size_t base = (size_t)blockIdx.x * 128;

    for (int i = tid; i < DD * 3; i += 128) sal[i] = alpha[i];

    float a[3][4];
#pragma unroll
    for (int h = 0; h < 3; h++)
#pragma unroll
        for (int u = 0; u < 4; u++) a[h][u] = 0.f;
    float sq = 0.f;

#pragma unroll
    for (int c = 0; c < 4; c++) {
        __syncthreads();
#pragma unroll
        for (int q = tid; q < 1024; q += 128) {
            int tok = q >> 3, v = q & 7;
            float4 f = *reinterpret_cast<const float4*>(
                pts + (base + tok) * DD + c * 32 + v * 4);
            tile[tok][v * 4 + 0] = f.x;
            tile[tok][v * 4 + 1] = f.y;
            tile[tok][v * 4 + 2] = f.z;
            tile[tok][v * 4 + 3] = f.w;
        }
        __syncthreads();
        const float* p = tile[tid];
#pragma unroll
        for (int j = 0; j < 32; j += 4) {
            int d = c * 32 + j;
#pragma unroll
            for (int u = 0; u < 4; u++) {
                float pv = p[j + u];
                a[0][u] = __fmaf_rn(pv, sal[(d + u) * 3 + 0], a[0][u]);
                a[1][u] = __fmaf_rn(pv, sal[(d + u) * 3 + 1], a[1][u]);
                a[2][u] = __fmaf_rn(pv, sal[(d + u) * 3 + 2], a[2][u]);
                sq      = __fmaf_rn(pv, pv, sq);
            }
        }
    }

    float k0 = __fadd_rn(__fadd_rn(a[0][0], a[0][1]), __fadd_rn(a[0][2], a[0][3]));
    float k1 = __fadd_rn(__fadd_rn(a[1][0], a[1][1]), __fadd_rn(a[1][2], a[1][3]));
    float k2 = __fadd_rn(__fadd_rn(a[2][0], a[2][1]), __fadd_rn(a[2][2], a[2][3]));
    float key = __fadd_rn(__fadd_rn(k0, __fmul_rn(2.f, k1)), __fmul_rn(4.f, k2));
    float nrm = __fsqrt_rn(sq);

    int gtok = (int)base + tid;
    ulonglong2 it;
    it.x = ((unsigned long long)fmono(key) << 32) | (unsigned long long)fmono(nrm);
    it.y = (unsigned long long)(gtok & (LL - 1));
    g_items[gtok] = it;
}

// ---------------------------------------------------------------------------
// Stage 1: full bitonic sort of each 2048 tile (k = 2..2048).
// ---------------------------------------------------------------------------
__global__ void __launch_bounds__(1024) bitonic_shared_first() {
    __shared__ ulonglong2 s[TILE];
    int base = blockIdx.x * TILE;
    int tid  = threadIdx.x;
    ulonglong2 x = g_items[base + tid];
    ulonglong2 y = g_items[base + tid + 1024];

#pragma unroll
    for (int k = 2; k <= 32; k <<= 1) {
        bool asc = (tid & k) == 0;
#pragma unroll
        for (int j = k >> 1; j; j >>= 1) {
            ulonglong2 ox = shfl_item(x, j), oy = shfl_item(y, j);
            bool wmin = ((tid & j) == 0) == asc;
            if (item_gt(x, ox) == wmin) x = ox;
            if (item_gt(y, oy) == wmin) y = oy;
        }
    }

    for (int k = 64; k <= TILE; k <<= 1) {
        s[tid] = x; s[tid + 1024] = y;
        __syncthreads();
        for (int j = k >> 1; j >= 32; j >>= 1) {
            int i = 2 * tid - (tid & (j - 1));
            int l = i + j;
            bool asc = (((unsigned)(base + i) & (LL - 1)) & (unsigned)k) == 0;
            ulonglong2 a = s[i], b = s[l];
            if (item_gt(a, b) == asc) { s[i] = b; s[l] = a; }
            __syncthreads();
        }
        x = s[tid]; y = s[tid + 1024];
        bool ascx = (((unsigned)(base + tid) & (LL - 1)) & (unsigned)k) == 0;
        bool ascy = (((unsigned)(base + tid + 1024) & (LL - 1)) & (unsigned)k) == 0;
#pragma unroll
        for (int j = 16; j; j >>= 1) {
            ulonglong2 ox = shfl_item(x, j), oy = shfl_item(y, j);
            bool wminx = ((tid & j) == 0) == ascx;
            bool wminy = ((tid & j) == 0) == ascy;
            if (item_gt(x, ox) == wminx) x = ox;
            if (item_gt(y, oy) == wminy) y = oy;
        }
    }
    g_items[base + tid] = x;
    g_items[base + tid + 1024] = y;
}

// ---------------------------------------------------------------------------
// Fused global pass for stage k: all strides >= 2048 in registers.
// ---------------------------------------------------------------------------
template <int M>
__global__ void __launch_bounds__(256) bitonic_global_fused(int k) {
    int g = blockIdx.x * blockDim.x + threadIdx.x;
    int high = g >> 11, low = g & 2047;
    unsigned base = (unsigned)high * (M * 2048) + (unsigned)low;

    ulonglong2 v[M];
#pragma unroll
    for (int t = 0; t < M; t++) v[t] = g_items[base + t * 2048];

    bool asc = ((base & (LL - 1)) & (unsigned)k) == 0;
#pragma unroll
    for (int s = M / 2; s; s >>= 1) {
#pragma unroll
        for (int t = 0; t < M; t++) {
            if (!(t & s)) ce(v[t], v[t | s], asc);
        }
    }
#pragma unroll
    for (int t = 0; t < M; t++) g_items[base + t * 2048] = v[t];
}

// ---------------------------------------------------------------------------
// Tile merge for stage k (k > TILE, uniform direction). 512 threads x 4:
// strides 1024,512 in regs; 256..32 in smem; 16..1 via shuffles.
// ---------------------------------------------------------------------------
__global__ void __launch_bounds__(512) bitonic_shared_merge(int k) {
    __shared__ ulonglong2 s[TILE];
    int base = blockIdx.x * TILE;
    int t = threadIdx.x;
    bool asc = (((unsigned)base & (LL - 1)) & (unsigned)k) == 0;

    ulonglong2 v[4];
#pragma unroll
    for (int i = 0; i < 4; i++) v[i] = g_items[base + t + i * 512];

    ce(v[0], v[2], asc); ce(v[1], v[3], asc);
    ce(v[0], v[1], asc); ce(v[2], v[3], asc);

#pragma unroll
    for (int i = 0; i < 4; i++) s[t + i * 512] = v[i];
    __syncthreads();

    for (int j = 256; j >= 32; j >>= 1) {
#pragma unroll
        for (int qq = 0; qq < 2; qq++) {
            int q = t + qq * 512;
            int i = 2 * q - (q & (j - 1));
            int l = i + j;
            ulonglong2 a = s[i], b = s[l];
            if (item_gt(a, b) == asc) { s[i] = b; s[l] = a; }
        }
        __syncthreads();
    }

    int w = t >> 5, l = t & 31;
#pragma unroll
    for (int c = 0; c < 4; c++) {
        int idx = w * 128 + c * 32 + l;
        ulonglong2 x = s[idx];
#pragma unroll
        for (int j = 16; j; j >>= 1) {
            ulonglong2 ox = shfl_item(x, j);
            bool wmin = ((l & j) == 0) == asc;
            if (item_gt(x, ox) == wmin) x = ox;
        }
        g_items[base + idx] = x;
    }
}

// ---------------------------------------------------------------------------
// FINAL merge (k = 32768, asc) fused with output: finish the sort, deposit
// source indices in smem ordered by final position, then WARP-PER-ROW copy
// (coalesced 512B accesses both sides; unroll 4 rows for MLP).
// ---------------------------------------------------------------------------
__global__ void __launch_bounds__(512) bitonic_merge_final(const float* __restrict__ pts,
                                                           float* __restrict__ out,
                                                           int write_idx) {
    __shared__ ulonglong2 s[TILE];
    __shared__ int srcs[TILE];
    int base = blockIdx.x * TILE;
    int t = threadIdx.x;
    const bool asc = true;  // k == LL -> ascending everywhere

    ulonglong2 v[4];
#pragma unroll
    for (int i = 0; i < 4; i++) v[i] = g_items[base + t + i * 512];

    ce(v[0], v[2], asc); ce(v[1], v[3], asc);
    ce(v[0], v[1], asc); ce(v[2], v[3], asc);

#pragma unroll
    for (int i = 0; i < 4; i++) s[t + i * 512] = v[i];
    __syncthreads();

    for (int j = 256; j >= 32; j >>= 1) {
#pragma unroll
        for (int qq = 0; qq < 2; qq++) {
            int q = t + qq * 512;
            int i = 2 * q - (q & (j - 1));
            int l = i + j;
            ulonglong2 a = s[i], b = s[l];
            if (item_gt(a, b) == asc) { s[i] = b; s[l] = a; }
        }
        __syncthreads();
    }

    int w = t >> 5, l = t & 31;
#pragma unroll
    for (int c = 0; c < 4; c++) {
        int idx = w * 128 + c * 32 + l;
        ulonglong2 x = s[idx];
#pragma unroll
        for (int j = 16; j; j >>= 1) {
            ulonglong2 ox = shfl_item(x, j);
            bool wmin = ((l & j) == 0) == asc;
            if (item_gt(x, ox) == wmin) x = ox;
        }
        srcs[idx] = (int)x.y;
    }
    __syncthreads();

    // index tail (coalesced)
    if (write_idx) {
#pragma unroll
        for (int i = 0; i < 4; i++) {
            int idx = t + i * 512;
            out[(size_t)NTOK * DD + base + idx] = (float)srcs[idx];
        }
    }

    // warp-per-row copy: 16 warps x 128 rows, 4 rows in flight per warp
    int b = base >> 15;  // tile lies within one batch
    const float4* pb = reinterpret_cast<const float4*>(pts + (size_t)b * LL * DD);
    float4* ob = reinterpret_cast<float4*>(out);
    for (int r = w; r < TILE; r += 64) {
        int s0 = srcs[r], s1 = srcs[r + 16], s2 = srcs[r + 32], s3 = srcs[r + 48];
        float4 v0 = pb[(size_t)s0 * 32 + l];
        float4 v1 = pb[(size_t)s1 * 32 + l];
        float4 v2 = pb[(size_t)s2 * 32 + l];
        float4 v3 = pb[(size_t)s3 * 32 + l];
        ob[(size_t)(base + r) * 32 + l]      = v0;
        ob[(size_t)(base + r + 16) * 32 + l] = v1;
        ob[(size_t)(base + r + 32) * 32 + l] = v2;
        ob[(size_t)(base + r + 48) * 32 + l] = v3;
    }
}

extern "C" void kernel_launch(void* const* d_in, const int* in_sizes, int n_in,
                              void* d_out, int out_size) {
    (void)n_in;
    const float* pts   = (const float*)d_in[0];
    const float* alpha = (const float*)d_in[1];
    if (in_sizes[0] < in_sizes[1]) { pts = (const float*)d_in[1]; alpha = (const float*)d_in[0]; }

    float* out = (float*)d_out;
    int write_idx = (out_size >= NTOK * DD + NTOK) ? 1 : 0;

    key_kernel<<<NTOK / 128, 128>>>(pts, alpha);

    bitonic_shared_first<<<NTILES, 1024>>>();

    bitonic_global_fused<2><<<(NTOK / 2) / 256, 256>>>(4096);
    bitonic_shared_merge<<<NTILES, 512>>>(4096);

    bitonic_global_fused<4><<<(NTOK / 4) / 256, 256>>>(8192);
    bitonic_shared_merge<<<NTILES, 512>>>(8192);

    bitonic_global_fused<8><<<(NTOK / 8) / 256, 256>>>(16384);
    bitonic_shared_merge<<<NTILES, 512>>>(16384);

    bitonic_global_fused<16><<<(NTOK / 16) / 256, 256>>>(32768);
    bitonic_merge_final<<<NTILES, 512>>>(pts, out, write_idx);
}

// round 11
// speedup vs baseline: 2.1032x; 1.0323x over previous
#include <cuda_runtime.h>

#define BB 8
#define LL 32768
#define DD 128
#define NTOK (BB * LL)
#define TILE 2048
#define NTILES (NTOK / TILE)

__device__ ulonglong2 g_items[NTOK];
__device__ int g_inv[NTOK];   // source row -> final position

__device__ __forceinline__ unsigned int fmono(float f) {
    unsigned int b = __float_as_uint(f);
    return (b & 0x80000000u) ? ~b : (b | 0x80000000u);
}
__device__ __forceinline__ bool item_gt(const ulonglong2& a, const ulonglong2& b) {
    return (a.x > b.x) || (a.x == b.x && a.y > b.y);
}
__device__ __forceinline__ void ce(ulonglong2& a, ulonglong2& b, bool asc) {
    if (item_gt(a, b) == asc) { ulonglong2 t = a; a = b; b = t; }
}
__device__ __forceinline__ ulonglong2 shfl_item(ulonglong2 v, int m) {
    ulonglong2 o;
    o.x = __shfl_xor_sync(0xffffffffu, v.x, m);
    o.y = __shfl_xor_sync(0xffffffffu, v.y, m);
    return o;
}

// ---------------------------------------------------------------------------
// Key kernel — rounding model LOCKED (R5/R6 bit-exact, C_A): 4 interleaved
// FMA accumulators (u = d mod 4), ascending d, combine (a0+a1)+(a2+a3);
// key = (k0 + 2*k1) + 4*k2. smem-staged coalesced loads (R9 lesson: never
// per-lane row reads).
// ---------------------------------------------------------------------------
__global__ void __launch_bounds__(128) key_kernel(const float* __restrict__ pts,
                                                  const float* __restrict__ alpha) {
    __shared__ float sal[DD * 3];
    __shared__ float tile[128][33];
    int tid = threadIdx.x;
    size_t base = (size_t)blockIdx.x * 128;

    for (int i = tid; i < DD * 3; i += 128) sal[i] = alpha[i];

    float a[3][4];
#pragma unroll
    for (int h = 0; h < 3; h++)
#pragma unroll
        for (int u = 0; u < 4; u++) a[h][u] = 0.f;
    float sq = 0.f;

#pragma unroll
    for (int c = 0; c < 4; c++) {
        __syncthreads();
#pragma unroll
        for (int q = tid; q < 1024; q += 128) {
            int tok = q >> 3, v = q & 7;
            float4 f = *reinterpret_cast<const float4*>(
                pts + (base + tok) * DD + c * 32 + v * 4);
            tile[tok][v * 4 + 0] = f.x;
            tile[tok][v * 4 + 1] = f.y;
            tile[tok][v * 4 + 2] = f.z;
            tile[tok][v * 4 + 3] = f.w;
        }
        __syncthreads();
        const float* p = tile[tid];
#pragma unroll
        for (int j = 0; j < 32; j += 4) {
            int d = c * 32 + j;
#pragma unroll
            for (int u = 0; u < 4; u++) {
                float pv = p[j + u];
                a[0][u] = __fmaf_rn(pv, sal[(d + u) * 3 + 0], a[0][u]);
                a[1][u] = __fmaf_rn(pv, sal[(d + u) * 3 + 1], a[1][u]);
                a[2][u] = __fmaf_rn(pv, sal[(d + u) * 3 + 2], a[2][u]);
                sq      = __fmaf_rn(pv, pv, sq);
            }
        }
    }

    float k0 = __fadd_rn(__fadd_rn(a[0][0], a[0][1]), __fadd_rn(a[0][2], a[0][3]));
    float k1 = __fadd_rn(__fadd_rn(a[1][0], a[1][1]), __fadd_rn(a[1][2], a[1][3]));
    float k2 = __fadd_rn(__fadd_rn(a[2][0], a[2][1]), __fadd_rn(a[2][2], a[2][3]));
    float key = __fadd_rn(__fadd_rn(k0, __fmul_rn(2.f, k1)), __fmul_rn(4.f, k2));
    float nrm = __fsqrt_rn(sq);

    int gtok = (int)base + tid;
    ulonglong2 it;
    it.x = ((unsigned long long)fmono(key) << 32) | (unsigned long long)fmono(nrm);
    it.y = (unsigned long long)(gtok & (LL - 1));
    g_items[gtok] = it;
}

// ---------------------------------------------------------------------------
// Stage 1: full bitonic sort of each 2048 tile (k = 2..2048).
// ---------------------------------------------------------------------------
__global__ void __launch_bounds__(1024) bitonic_shared_first() {
    __shared__ ulonglong2 s[TILE];
    int base = blockIdx.x * TILE;
    int tid  = threadIdx.x;
    ulonglong2 x = g_items[base + tid];
    ulonglong2 y = g_items[base + tid + 1024];

#pragma unroll
    for (int k = 2; k <= 32; k <<= 1) {
        bool asc = (tid & k) == 0;
#pragma unroll
        for (int j = k >> 1; j; j >>= 1) {
            ulonglong2 ox = shfl_item(x, j), oy = shfl_item(y, j);
            bool wmin = ((tid & j) == 0) == asc;
            if (item_gt(x, ox) == wmin) x = ox;
            if (item_gt(y, oy) == wmin) y = oy;
        }
    }

    for (int k = 64; k <= TILE; k <<= 1) {
        s[tid] = x; s[tid + 1024] = y;
        __syncthreads();
        for (int j = k >> 1; j >= 32; j >>= 1) {
            int i = 2 * tid - (tid & (j - 1));
            int l = i + j;
            bool asc = (((unsigned)(base + i) & (LL - 1)) & (unsigned)k) == 0;
            ulonglong2 a = s[i], b = s[l];
            if (item_gt(a, b) == asc) { s[i] = b; s[l] = a; }
            __syncthreads();
        }
        x = s[tid]; y = s[tid + 1024];
        bool ascx = (((unsigned)(base + tid) & (LL - 1)) & (unsigned)k) == 0;
        bool ascy = (((unsigned)(base + tid + 1024) & (LL - 1)) & (unsigned)k) == 0;
#pragma unroll
        for (int j = 16; j; j >>= 1) {
            ulonglong2 ox = shfl_item(x, j), oy = shfl_item(y, j);
            bool wminx = ((tid & j) == 0) == ascx;
            bool wminy = ((tid & j) == 0) == ascy;
            if (item_gt(x, ox) == wminx) x = ox;
            if (item_gt(y, oy) == wminy) y = oy;
        }
    }
    g_items[base + tid] = x;
    g_items[base + tid + 1024] = y;
}

// ---------------------------------------------------------------------------
// Fused global pass for stage k: all strides >= 2048 in registers.
// ---------------------------------------------------------------------------
template <int M>
__global__ void __launch_bounds__(256) bitonic_global_fused(int k) {
    int g = blockIdx.x * blockDim.x + threadIdx.x;
    int high = g >> 11, low = g & 2047;
    unsigned base = (unsigned)high * (M * 2048) + (unsigned)low;

    ulonglong2 v[M];
#pragma unroll
    for (int t = 0; t < M; t++) v[t] = g_items[base + t * 2048];

    bool asc = ((base & (LL - 1)) & (unsigned)k) == 0;
#pragma unroll
    for (int s = M / 2; s; s >>= 1) {
#pragma unroll
        for (int t = 0; t < M; t++) {
            if (!(t & s)) ce(v[t], v[t | s], asc);
        }
    }
#pragma unroll
    for (int t = 0; t < M; t++) g_items[base + t * 2048] = v[t];
}

// ---------------------------------------------------------------------------
// Tile merge for stage k (k > TILE, uniform asc). 256 threads x 8 elements,
// ONE barrier. Phase 1: layout t+256i -> strides 1024(i^4),512(i^2),256(i^1)
// in registers. Phase 2: warp-per-256-chunk, layout 256w+l+32i -> strides
// 128,64,32 in registers, 16..1 via shuffles. Descending stride order and
// disjoint within-stride pairs preserved -> network identical.
// WRITE_INV: final stage emits inverse permutation instead of items.
// ---------------------------------------------------------------------------
template <int WRITE_INV>
__global__ void __launch_bounds__(256) bitonic_shared_merge(int k, int write_idx_tail,
                                                            float* __restrict__ out) {
    __shared__ ulonglong2 s[TILE];
    int base = blockIdx.x * TILE;
    int t = threadIdx.x;
    bool asc = WRITE_INV ? true : ((((unsigned)base & (LL - 1)) & (unsigned)k) == 0);

    ulonglong2 v[8];
#pragma unroll
    for (int i = 0; i < 8; i++) v[i] = g_items[base + t + i * 256];

    // strides 1024, 512, 256
#pragma unroll
    for (int i = 0; i < 4; i++) ce(v[i], v[i + 4], asc);
#pragma unroll
    for (int i = 0; i < 8; i++) if (!(i & 2)) ce(v[i], v[i | 2], asc);
#pragma unroll
    for (int i = 0; i < 8; i += 2) ce(v[i], v[i + 1], asc);

#pragma unroll
    for (int i = 0; i < 8; i++) s[t + i * 256] = v[i];
    __syncthreads();

    int w = t >> 5, l = t & 31;
    int chunk = w * 256;
#pragma unroll
    for (int i = 0; i < 8; i++) v[i] = s[chunk + l + i * 32];

    // strides 128, 64, 32
#pragma unroll
    for (int i = 0; i < 4; i++) ce(v[i], v[i + 4], asc);
#pragma unroll
    for (int i = 0; i < 8; i++) if (!(i & 2)) ce(v[i], v[i | 2], asc);
#pragma unroll
    for (int i = 0; i < 8; i += 2) ce(v[i], v[i + 1], asc);

    // strides 16..1 via shuffles
#pragma unroll
    for (int i = 0; i < 8; i++) {
        ulonglong2 x = v[i];
#pragma unroll
        for (int j = 16; j; j >>= 1) {
            ulonglong2 ox = shfl_item(x, j);
            bool wmin = ((l & j) == 0) == asc;
            if (item_gt(x, ox) == wmin) x = ox;
        }
        int e = base + chunk + l + i * 32;
        if (WRITE_INV) {
            int b = e >> 15;
            g_inv[b * LL + (int)x.y] = e;
            if (write_idx_tail) out[(size_t)NTOK * DD + e] = (float)(int)x.y;
        } else {
            g_items[e] = x;
        }
    }
}

// ---------------------------------------------------------------------------
// Scatter: linear read of pts (streaming), random full-row write via g_inv.
// One warp per source row (R8-proven pattern).
// ---------------------------------------------------------------------------
__global__ void __launch_bounds__(256) scatter_kernel(const float* __restrict__ pts,
                                                      float* __restrict__ out) {
    int gwarp = (blockIdx.x * blockDim.x + threadIdx.x) >> 5;
    int lane  = threadIdx.x & 31;
    if (gwarp >= NTOK) return;
    int dst = g_inv[gwarp];  // broadcast across warp
    const float4* src = reinterpret_cast<const float4*>(pts + (size_t)gwarp * DD);
    float4* d = reinterpret_cast<float4*>(out + (size_t)dst * DD);
    d[lane] = src[lane];
}

extern "C" void kernel_launch(void* const* d_in, const int* in_sizes, int n_in,
                              void* d_out, int out_size) {
    (void)n_in;
    const float* pts   = (const float*)d_in[0];
    const float* alpha = (const float*)d_in[1];
    if (in_sizes[0] < in_sizes[1]) { pts = (const float*)d_in[1]; alpha = (const float*)d_in[0]; }

    float* out = (float*)d_out;
    int write_idx = (out_size >= NTOK * DD + NTOK) ? 1 : 0;

    key_kernel<<<NTOK / 128, 128>>>(pts, alpha);

    bitonic_shared_first<<<NTILES, 1024>>>();

    bitonic_global_fused<2><<<(NTOK / 2) / 256, 256>>>(4096);
    bitonic_shared_merge<0><<<NTILES, 256>>>(4096, 0, out);

    bitonic_global_fused<4><<<(NTOK / 4) / 256, 256>>>(8192);
    bitonic_shared_merge<0><<<NTILES, 256>>>(8192, 0, out);

    bitonic_global_fused<8><<<(NTOK / 8) / 256, 256>>>(16384);
    bitonic_shared_merge<0><<<NTILES, 256>>>(16384, 0, out);

    bitonic_global_fused<16><<<(NTOK / 16) / 256, 256>>>(32768);
    bitonic_shared_merge<1><<<NTILES, 256>>>(32768, write_idx, out);

    scatter_kernel<<<NTOK / 8, 256>>>(pts, out);
}

// round 12
// speedup vs baseline: 2.1983x; 1.0452x over previous
#include <cuda_runtime.h>

#define BB 8
#define LL 32768
#define DD 128
#define NTOK (BB * LL)
#define TILE 2048
#define NTILES (NTOK / TILE)

__device__ ulonglong2 g_items[NTOK];
__device__ ulonglong2 g_items2[NTOK];  // ping-pong buffer for merge rounds
__device__ int g_inv[NTOK];            // source row -> final position

__device__ __forceinline__ unsigned int fmono(float f) {
    unsigned int b = __float_as_uint(f);
    return (b & 0x80000000u) ? ~b : (b | 0x80000000u);
}
__device__ __forceinline__ bool item_gt(const ulonglong2& a, const ulonglong2& b) {
    return (a.x > b.x) || (a.x == b.x && a.y > b.y);
}
__device__ __forceinline__ ulonglong2 shfl_item(ulonglong2 v, int m) {
    ulonglong2 o;
    o.x = __shfl_xor_sync(0xffffffffu, v.x, m);
    o.y = __shfl_xor_sync(0xffffffffu, v.y, m);
    return o;
}

// ---------------------------------------------------------------------------
// Key kernel — rounding model LOCKED (R5/R6 bit-exact, C_A): 4 interleaved
// FMA accumulators (u = d mod 4), ascending d, combine (a0+a1)+(a2+a3);
// key = (k0 + 2*k1) + 4*k2. smem-staged coalesced loads (R9 lesson: never
// per-lane row reads).
// ---------------------------------------------------------------------------
__global__ void __launch_bounds__(128) key_kernel(const float* __restrict__ pts,
                                                  const float* __restrict__ alpha) {
    __shared__ float sal[DD * 3];
    __shared__ float tile[128][33];
    int tid = threadIdx.x;
    size_t base = (size_t)blockIdx.x * 128;

    for (int i = tid; i < DD * 3; i += 128) sal[i] = alpha[i];

    float a[3][4];
#pragma unroll
    for (int h = 0; h < 3; h++)
#pragma unroll
        for (int u = 0; u < 4; u++) a[h][u] = 0.f;
    float sq = 0.f;

#pragma unroll
    for (int c = 0; c < 4; c++) {
        __syncthreads();
#pragma unroll
        for (int q = tid; q < 1024; q += 128) {
            int tok = q >> 3, v = q & 7;
            float4 f = *reinterpret_cast<const float4*>(
                pts + (base + tok) * DD + c * 32 + v * 4);
            tile[tok][v * 4 + 0] = f.x;
            tile[tok][v * 4 + 1] = f.y;
            tile[tok][v * 4 + 2] = f.z;
            tile[tok][v * 4 + 3] = f.w;
        }
        __syncthreads();
        const float* p = tile[tid];
#pragma unroll
        for (int j = 0; j < 32; j += 4) {
            int d = c * 32 + j;
#pragma unroll
            for (int u = 0; u < 4; u++) {
                float pv = p[j + u];
                a[0][u] = __fmaf_rn(pv, sal[(d + u) * 3 + 0], a[0][u]);
                a[1][u] = __fmaf_rn(pv, sal[(d + u) * 3 + 1], a[1][u]);
                a[2][u] = __fmaf_rn(pv, sal[(d + u) * 3 + 2], a[2][u]);
                sq      = __fmaf_rn(pv, pv, sq);
            }
        }
    }

    float k0 = __fadd_rn(__fadd_rn(a[0][0], a[0][1]), __fadd_rn(a[0][2], a[0][3]));
    float k1 = __fadd_rn(__fadd_rn(a[1][0], a[1][1]), __fadd_rn(a[1][2], a[1][3]));
    float k2 = __fadd_rn(__fadd_rn(a[2][0], a[2][1]), __fadd_rn(a[2][2], a[2][3]));
    float key = __fadd_rn(__fadd_rn(k0, __fmul_rn(2.f, k1)), __fmul_rn(4.f, k2));
    float nrm = __fsqrt_rn(sq);

    int gtok = (int)base + tid;
    ulonglong2 it;
    it.x = ((unsigned long long)fmono(key) << 32) | (unsigned long long)fmono(nrm);
    it.y = (unsigned long long)(gtok & (LL - 1));
    g_items[gtok] = it;
}

// ---------------------------------------------------------------------------
// Stage 1: full bitonic sort of each 2048 tile, final stage forced ASCENDING
// (merge rounds need all runs ascending; network remains a valid sort).
// ---------------------------------------------------------------------------
__global__ void __launch_bounds__(1024) bitonic_shared_first() {
    __shared__ ulonglong2 s[TILE];
    int base = blockIdx.x * TILE;
    int tid  = threadIdx.x;
    ulonglong2 x = g_items[base + tid];
    ulonglong2 y = g_items[base + tid + 1024];

#pragma unroll
    for (int k = 2; k <= 32; k <<= 1) {
        bool asc = (tid & k) == 0;
#pragma unroll
        for (int j = k >> 1; j; j >>= 1) {
            ulonglong2 ox = shfl_item(x, j), oy = shfl_item(y, j);
            bool wmin = ((tid & j) == 0) == asc;
            if (item_gt(x, ox) == wmin) x = ox;
            if (item_gt(y, oy) == wmin) y = oy;
        }
    }

    for (int k = 64; k <= TILE; k <<= 1) {
        s[tid] = x; s[tid + 1024] = y;
        __syncthreads();
        for (int j = k >> 1; j >= 32; j >>= 1) {
            int i = 2 * tid - (tid & (j - 1));
            int l = i + j;
            bool asc = (k == TILE) ? true
                     : ((((unsigned)(base + i) & (LL - 1)) & (unsigned)k) == 0);
            ulonglong2 a = s[i], b = s[l];
            if (item_gt(a, b) == asc) { s[i] = b; s[l] = a; }
            __syncthreads();
        }
        x = s[tid]; y = s[tid + 1024];
        bool ascx = (k == TILE) ? true
                  : ((((unsigned)(base + tid) & (LL - 1)) & (unsigned)k) == 0);
        bool ascy = (k == TILE) ? true
                  : ((((unsigned)(base + tid + 1024) & (LL - 1)) & (unsigned)k) == 0);
#pragma unroll
        for (int j = 16; j; j >>= 1) {
            ulonglong2 ox = shfl_item(x, j), oy = shfl_item(y, j);
            bool wminx = ((tid & j) == 0) == ascx;
            bool wminy = ((tid & j) == 0) == ascy;
            if (item_gt(x, ox) == wminx) x = ox;
            if (item_gt(y, oy) == wminy) y = oy;
        }
    }
    g_items[base + tid] = x;
    g_items[base + tid + 1024] = y;
}

// ---------------------------------------------------------------------------
// Warp-parallel merge-path diagonal search: find a* = #elements of A among the
// first d of merge(A,B) (|A|=|B|=R, keys strictly unique). Ballot 32-ary
// search: ~3 iterations instead of ~14 serial dependent loads.
// ---------------------------------------------------------------------------
__device__ int mp_search_warp(const ulonglong2* __restrict__ A,
                              const ulonglong2* __restrict__ B,
                              int R, int d) {
    int lane = threadIdx.x & 31;
    int lo = max(0, d - R);
    int hi = min(d, R);
    while (hi > lo) {
        int span = hi - lo;              // candidates a in (lo, hi]
        int chunk = (span + 31) >> 5;    // ceil(span/32)
        int a = lo + 1 + lane * chunk;
        bool valid = a <= hi;
        bool p = false;
        if (valid) p = item_gt(B[d - a], A[a - 1]);   // A[a-1] < B[d-a]
        unsigned mt = __ballot_sync(0xffffffffu, valid && p);
        unsigned mf = __ballot_sync(0xffffffffu, valid && !p);
        int nlo = lo, nhi = hi;
        if (mt) { int i = 31 - __clz(mt); nlo = lo + 1 + i * chunk; }
        if (mf) { int i = __ffs(mf) - 1;  nhi = lo + i * chunk; }
        lo = nlo; hi = nhi;
    }
    return lo;
}

// ---------------------------------------------------------------------------
// Merge round: pairs of ascending runs of size R -> runs of 2R. Each block
// produces TILE=2048 outputs. Segments staged in smem (coalesced), per-thread
// local merge path (4 outputs), results re-staged in smem, coalesced write.
// FINAL round writes inverse permutation + index tail instead.
// ---------------------------------------------------------------------------
template <int FINAL>
__global__ void __launch_bounds__(512) merge_round(int R, int flip,
                                                   float* __restrict__ out,
                                                   int write_idx) {
    __shared__ ulonglong2 sIn[TILE];
    __shared__ int sPart[2];
    const ulonglong2* __restrict__ src = flip ? g_items2 : g_items;
    ulonglong2* __restrict__ dst = flip ? g_items : g_items2;

    int t = threadIdx.x;
    int blockOut = blockIdx.x * TILE;
    int pairSize = 2 * R;
    int pairIdx = blockOut / pairSize;
    int o = blockOut & (pairSize - 1);
    const ulonglong2* A = src + (size_t)pairIdx * pairSize;
    const ulonglong2* B = A + R;

    int w = t >> 5;
    if (w == 0) {
        int a0 = mp_search_warp(A, B, R, o);
        if ((t & 31) == 0) sPart[0] = a0;
    } else if (w == 1) {
        int a1 = mp_search_warp(A, B, R, o + TILE);
        if ((t & 31) == 0) sPart[1] = a1;
    }
    __syncthreads();
    int a0 = sPart[0], a1 = sPart[1];
    int b0 = o - a0;
    int la = a1 - a0, lb = TILE - la;

    for (int i = t; i < la; i += 512) sIn[i] = A[a0 + i];
    for (int i = t; i < lb; i += 512) sIn[la + i] = B[b0 + i];
    __syncthreads();

    // local partition for this thread's 4 outputs
    int dl = t * 4;
    int alo = max(0, dl - lb), ahi = min(dl, la);
    while (alo < ahi) {
        int mid = (alo + ahi + 1) >> 1;
        if (item_gt(sIn[la + dl - mid], sIn[mid - 1])) alo = mid; else ahi = mid - 1;
    }
    int ai = alo, bi = dl - alo;

    ulonglong2 v[4];
#pragma unroll
    for (int i = 0; i < 4; i++) {
        bool takeA;
        if (ai >= la) takeA = false;
        else if (bi >= lb) takeA = true;
        else takeA = item_gt(sIn[la + bi], sIn[ai]);  // A < B (keys unique)
        v[i] = takeA ? sIn[ai++] : sIn[la + bi++];
    }

    if (FINAL) {
        int batch = blockOut >> 15;
#pragma unroll
        for (int i = 0; i < 4; i++) {
            int e = blockOut + dl + i;
            g_inv[batch * LL + (int)v[i].y] = e;
            if (write_idx) out[(size_t)NTOK * DD + e] = (float)(int)v[i].y;
        }
    } else {
        __syncthreads();
#pragma unroll
        for (int i = 0; i < 4; i++) sIn[dl + i] = v[i];
        __syncthreads();
#pragma unroll
        for (int i = 0; i < 4; i++) {
            int idx = t + i * 512;
            dst[blockOut + idx] = sIn[idx];
        }
    }
}

// ---------------------------------------------------------------------------
// Scatter: linear read of pts (streaming), random full-row write via g_inv.
// One warp per source row (R8-proven pattern).
// ---------------------------------------------------------------------------
__global__ void __launch_bounds__(256) scatter_kernel(const float* __restrict__ pts,
                                                      float* __restrict__ out) {
    int gwarp = (blockIdx.x * blockDim.x + threadIdx.x) >> 5;
    int lane  = threadIdx.x & 31;
    if (gwarp >= NTOK) return;
    int dst = g_inv[gwarp];  // broadcast across warp
    const float4* src = reinterpret_cast<const float4*>(pts + (size_t)gwarp * DD);
    float4* d = reinterpret_cast<float4*>(out + (size_t)dst * DD);
    d[lane] = src[lane];
}

extern "C" void kernel_launch(void* const* d_in, const int* in_sizes, int n_in,
                              void* d_out, int out_size) {
    (void)n_in;
    const float* pts   = (const float*)d_in[0];
    const float* alpha = (const float*)d_in[1];
    if (in_sizes[0] < in_sizes[1]) { pts = (const float*)d_in[1]; alpha = (const float*)d_in[0]; }

    float* out = (float*)d_out;
    int write_idx = (out_size >= NTOK * DD + NTOK) ? 1 : 0;

    key_kernel<<<NTOK / 128, 128>>>(pts, alpha);
    bitonic_shared_first<<<NTILES, 1024>>>();

    merge_round<0><<<NTILES, 512>>>(2048, 0, out, 0);   // items  -> items2
    merge_round<0><<<NTILES, 512>>>(4096, 1, out, 0);   // items2 -> items
    merge_round<0><<<NTILES, 512>>>(8192, 0, out, 0);   // items  -> items2
    merge_round<1><<<NTILES, 512>>>(16384, 1, out, write_idx);  // items2 -> g_inv

    scatter_kernel<<<NTOK / 8, 256>>>(pts, out);
}